// round 1
// baseline (speedup 1.0000x reference)
#include <cuda_runtime.h>

#define N_PULSES 64
#define BATCH    16384
#define N_STATES 21

// One warp per batch element; lane = EPG state index (lanes 21..31 are inert
// "virtual states" that only feed shuffles and never store).
__global__ __launch_bounds__(256) void epg_kernel(
    const float* __restrict__ flip,
    const float* __restrict__ phases,
    const float* __restrict__ T1,
    const float* __restrict__ T2,
    const float* __restrict__ B0,
    const float* __restrict__ B1,
    const void*  __restrict__ trp,
    float*       __restrict__ out)
{
    __shared__ float s_a[N_PULSES], s_cb[N_PULSES], s_sb[N_PULSES],
                     s_c2b[N_PULSES], s_s2b[N_PULSES];

    const int tid = threadIdx.x;
    if (tid < N_PULSES) {
        float b = phases[tid];
        float sb, cb;
        sincosf(b, &sb, &cb);          // precise: b in [0, 2pi]
        s_a[tid]   = flip[tid];
        s_cb[tid]  = cb;
        s_sb[tid]  = sb;
        s_c2b[tid] = cb * cb - sb * sb;
        s_s2b[tid] = 2.0f * cb * sb;
    }
    __syncthreads();

    const int w    = (blockIdx.x * blockDim.x + tid) >> 5;  // batch index
    const int lane = tid & 31;

    // TR may arrive as int32 or float32 scalar; sniff the bit pattern.
    float TR;
    {
        int   iv = *(const int*)trp;
        float fv = __int_as_float(iv);
        TR = (fv >= 1.0f && fv < 1.0e6f) ? fv : (float)iv;
    }

    const float t1 = T1[w], t2 = T2[w], b0 = B0[w], b1 = B1[w];
    const float E1 = __expf(-TR / t1);
    const float E2 = __expf(-TR / t2);
    const float one_m_E1 = 1.0f - E1;
    const float phi = 2.0f * 3.14159265358979323846f * b0 * TR * (1.0f / 1000.0f);
    float sp, cp;
    sincosf(phi, &sp, &cp);            // precise: phi can be O(500 rad)

    float Fpr = 0.f, Fpi = 0.f, Fmr = 0.f, Fmi = 0.f;
    float Z = (lane == 0) ? 1.0f : 0.0f;

    const size_t CS = (size_t)BATCH * N_STATES;             // component stride
    float* obase = out + (size_t)w * N_STATES + lane;
    const bool active = (lane < N_STATES);

    #pragma unroll 2
    for (int p = 0; p < N_PULSES; ++p) {
        // --- relaxation ---
        Fpr *= E2; Fpi *= E2; Fmr *= E2; Fmi *= E2;
        Z = E1 * Z + ((lane == 0) ? one_m_E1 : 0.0f);

        // --- off-resonance precession: Fp *= e^{+i phi}, Fm *= e^{-i phi} ---
        {
            float r = Fpr * cp - Fpi * sp;
            float i = Fpr * sp + Fpi * cp;
            Fpr = r; Fpi = i;
            r = Fmr * cp + Fmi * sp;
            i = Fmi * cp - Fmr * sp;
            Fmr = r; Fmi = i;
        }

        // --- RF pulse ---
        const float alpha_h = 0.5f * s_a[p] * b1;
        float sa, ca;
        __sincosf(alpha_h, &sa, &ca);  // small argument, fast path OK
        const float cb = s_cb[p],  sb = s_sb[p];
        const float c2 = s_c2b[p], s2 = s_s2b[p];
        const float caa = ca * ca, saa = sa * sa, casa = ca * sa;

        // conj(Fm) * e^{2ib}
        const float cme_r = Fmr * c2 + Fmi * s2;
        const float cme_i = Fmr * s2 - Fmi * c2;
        // i * Z * e^{ib}
        const float ize_r = -Z * sb;
        const float ize_i =  Z * cb;
        const float Fpn_r = caa * Fpr + saa * cme_r + casa * ize_r;
        const float Fpn_i = caa * Fpi + saa * cme_i + casa * ize_i;

        // conj(Fp) * e^{-2ib} = conj(Fp * e^{2ib})
        const float pe_r = Fpr * c2 - Fpi * s2;
        const float pe_i = Fpr * s2 + Fpi * c2;
        // -i * Z * e^{-ib} = (-Z sb, -Z cb)
        const float Fmn_r = saa * pe_r + caa * Fmr + casa * (-Z * sb);
        const float Fmn_i = -saa * pe_i + caa * Fmi + casa * (-Z * cb);

        // Z' = ca*sa*Im(Fp e^{-ib} - Fm e^{ib}) + (ca^2 - sa^2) Z
        const float Di = (Fpi * cb - Fpr * sb) - (Fmr * sb + Fmi * cb);
        const float Zn = casa * Di + (caa - saa) * Z;

        // --- gradient shift: Fp rolls +1 (state 0 := 0), Fm rolls -1 (last := 0)
        float nFpr = __shfl_up_sync(0xffffffffu, Fpn_r, 1);
        float nFpi = __shfl_up_sync(0xffffffffu, Fpn_i, 1);
        if (lane == 0) { nFpr = 0.f; nFpi = 0.f; }
        float nFmr = __shfl_down_sync(0xffffffffu, Fmn_r, 1);
        float nFmi = __shfl_down_sync(0xffffffffu, Fmn_i, 1);
        if (lane == N_STATES - 1) { nFmr = 0.f; nFmi = 0.f; }

        Fpr = nFpr; Fpi = nFpi; Fmr = nFmr; Fmi = nFmi; Z = Zn;

        // --- emit [Fp.re, Fp.im, Fm.re, Fm.im, Z] for this pulse ---
        if (active) {
            float* o = obase + (size_t)(p * 5) * CS;
            o[0]      = Fpr;
            o[CS]     = Fpi;
            o[2 * CS] = Fmr;
            o[3 * CS] = Fmi;
            o[4 * CS] = Z;
        }
    }
}

extern "C" void kernel_launch(void* const* d_in, const int* in_sizes, int n_in,
                              void* d_out, int out_size)
{
    const float* flip   = (const float*)d_in[0];
    const float* phases = (const float*)d_in[1];
    const float* T1     = (const float*)d_in[2];
    const float* T2     = (const float*)d_in[3];
    const float* B0     = (const float*)d_in[4];
    const float* B1     = (const float*)d_in[5];
    const void*  trp    = d_in[6];
    float* out = (float*)d_out;

    const int threads = 256;                       // 8 warps = 8 batch elements
    const int blocks  = (BATCH * 32) / threads;    // 2048 blocks
    epg_kernel<<<blocks, threads>>>(flip, phases, T1, T2, B0, B1, trp, out);
}

// round 2
// speedup vs baseline: 1.2272x; 1.2272x over previous
#include <cuda_runtime.h>

#define N_PULSES 64
#define BATCH    16384
#define N_STATES 21

typedef unsigned long long u64;

// ---- packed f32x2 helpers (Blackwell sm_100+: fma.rn.f32x2 etc.) ----
__device__ __forceinline__ u64 pk(float lo, float hi) {
    u64 r; asm("mov.b64 %0,{%1,%2};" : "=l"(r) : "f"(lo), "f"(hi)); return r;
}
__device__ __forceinline__ void upk(u64 v, float& a, float& b) {
    asm("mov.b64 {%0,%1},%2;" : "=f"(a), "=f"(b) : "l"(v));
}
__device__ __forceinline__ u64 fma2(u64 a, u64 b, u64 c) {
    u64 d; asm("fma.rn.f32x2 %0,%1,%2,%3;" : "=l"(d) : "l"(a), "l"(b), "l"(c)); return d;
}
__device__ __forceinline__ u64 mul2(u64 a, u64 b) {
    u64 d; asm("mul.rn.f32x2 %0,%1,%2;" : "=l"(d) : "l"(a), "l"(b)); return d;
}
#define NEG2(x) ((x) ^ 0x8000000080000000ULL)

__device__ __forceinline__ u64 shup64(u64 v) {
    float a, b; upk(v, a, b);
    a = __shfl_up_sync(0xffffffffu, a, 1);
    b = __shfl_up_sync(0xffffffffu, b, 1);
    return pk(a, b);
}
__device__ __forceinline__ u64 shdn64(u64 v) {
    float a, b; upk(v, a, b);
    a = __shfl_down_sync(0xffffffffu, a, 1);
    b = __shfl_down_sync(0xffffffffu, b, 1);
    return pk(a, b);
}

// One warp serves TWO batch rows; lane = EPG state; all state packed f32x2.
__global__ __launch_bounds__(128, 6) void epg_kernel(
    const float* __restrict__ flip,
    const float* __restrict__ phases,
    const float* __restrict__ T1,
    const float* __restrict__ T2,
    const float* __restrict__ B0,
    const float* __restrict__ B1,
    const void*  __restrict__ trp,
    float*       __restrict__ out)
{
    // Per-pulse broadcast constants, pre-packed as f32x2 pairs:
    // k[0] = {cb2, sb2}, k[1] = {nsb2, ncb2}, k[2] = {c2b2, s2b2}, k[3] = {ns2b2, nc2b2}
    __shared__ ulonglong2 s_k[N_PULSES][4];
    __shared__ float s_a[N_PULSES];

    const int tid = threadIdx.x;
    if (tid < N_PULSES) {
        float b = phases[tid];
        float sb, cb;
        sincosf(b, &sb, &cb);                 // precise: b in [0, 2pi]
        float c2b = cb * cb - sb * sb;
        float s2b = 2.0f * cb * sb;
        s_k[tid][0] = make_ulonglong2(pk(cb, cb),     pk(sb, sb));
        s_k[tid][1] = make_ulonglong2(pk(-sb, -sb),   pk(-cb, -cb));
        s_k[tid][2] = make_ulonglong2(pk(c2b, c2b),   pk(s2b, s2b));
        s_k[tid][3] = make_ulonglong2(pk(-s2b, -s2b), pk(-c2b, -c2b));
        s_a[tid] = flip[tid];
    }
    __syncthreads();

    const int gw   = (blockIdx.x * blockDim.x + tid) >> 5;   // warp id
    const int lane = tid & 31;
    const int w0 = gw * 2, w1 = w0 + 1;                      // two batch rows

    // TR may arrive as int32 or float32 scalar; sniff the bit pattern.
    float TR;
    {
        int   iv = *(const int*)trp;
        float fv = __int_as_float(iv);
        TR = (fv >= 1.0f && fv < 1.0e6f) ? fv : (float)iv;
    }

    const float E10 = __expf(-TR / T1[w0]);
    const float E11 = __expf(-TR / T1[w1]);
    const float E20 = __expf(-TR / T2[w0]);
    const float E21 = __expf(-TR / T2[w1]);
    const float PC  = 2.0f * 3.14159265358979323846f * (1.0f / 1000.0f) * TR;
    float sp0, cp0, sp1, cp1;
    sincosf(PC * B0[w0], &sp0, &cp0);         // precise: large argument
    sincosf(PC * B0[w1], &sp1, &cp1);
    const float b10 = B1[w0], b11 = B1[w1];

    // Loop-invariant packed constants
    const u64 E1p   = pk(E10, E11);
    const u64 cpE2  = pk(cp0 * E20, cp1 * E21);   // E2 relaxation fused into precession
    const u64 spE2  = pk(sp0 * E20, sp1 * E21);
    const u64 nspE2 = NEG2(spE2);
    const u64 addz  = (lane == 0) ? pk(1.0f - E10, 1.0f - E11) : 0ull;
    const u64 HALF  = pk(0.5f, 0.5f);
    const u64 NHALF = pk(-0.5f, -0.5f);

    u64 Fpr = 0, Fpi = 0, Fmr = 0, Fmi = 0;
    u64 Z = (lane == 0) ? pk(1.0f, 1.0f) : 0ull;

    const size_t CS = (size_t)BATCH * N_STATES;   // component stride (floats)
    float* o0 = out + (size_t)w0 * N_STATES + lane;
    float* o1 = o0 + N_STATES;
    const bool active = (lane < N_STATES);
    const bool l0     = (lane == 0);
    const bool llast  = (lane == N_STATES - 1);

    #pragma unroll 2
    for (int p = 0; p < N_PULSES; ++p) {
        const ulonglong2 k0 = s_k[p][0], k1 = s_k[p][1], k2 = s_k[p][2], k3 = s_k[p][3];
        const u64 cb2 = k0.x, sb2 = k0.y, nsb2 = k1.x, ncb2 = k1.y;
        const u64 c2b2 = k2.x, s2b2 = k2.y, ns2b2 = k3.x, nc2b2 = k3.y;

        // --- relaxation (E2) fused with off-resonance precession ---
        {
            u64 r  = fma2(Fpi, nspE2, mul2(Fpr, cpE2));
            u64 i  = fma2(Fpi, cpE2,  mul2(Fpr, spE2));
            u64 r2 = fma2(Fmi, spE2,  mul2(Fmr, cpE2));
            u64 i2 = fma2(Fmi, cpE2,  mul2(Fmr, nspE2));
            Fpr = r; Fpi = i; Fmr = r2; Fmi = i2;
        }
        Z = fma2(Z, E1p, addz);

        // --- RF pulse via half-angle identities ---
        const float a = s_a[p];
        float sa0, ca0, sa1, ca1;
        __sincosf(a * b10, &sa0, &ca0);       // alpha (full angle), small arg
        __sincosf(a * b11, &sa1, &ca1);
        const u64 c_al = pk(ca0, ca1);        // cos(alpha) = ca^2 - sa^2
        const u64 s_al = pk(sa0, sa1);
        const u64 caa  = fma2(c_al, HALF,  HALF);   // cos^2(a/2)
        const u64 saa  = fma2(c_al, NHALF, HALF);   // sin^2(a/2)
        const u64 casa = mul2(s_al, HALF);          // cos(a/2)sin(a/2)
        const u64 nsaa = NEG2(saa);

        // conj(Fm) * e^{2ib}
        const u64 cme_r = fma2(Fmi, s2b2,  mul2(Fmr, c2b2));
        const u64 cme_i = fma2(Fmi, nc2b2, mul2(Fmr, s2b2));
        // Fp * e^{2ib}  (conj gives the e^{-2ib} term)
        const u64 pe_r  = fma2(Fpi, ns2b2, mul2(Fpr, c2b2));
        const u64 pe_i  = fma2(Fpi, c2b2,  mul2(Fpr, s2b2));
        // i Z e^{ib} = (-Z sb, Z cb);  -i Z e^{-ib} = (-Z sb, -Z cb)
        const u64 mZsb = mul2(Z, nsb2);
        const u64 Zcb  = mul2(Z, cb2);
        const u64 mZcb = NEG2(Zcb);

        const u64 Fpn_r = fma2(casa, mZsb, fma2(saa,  cme_r, mul2(caa, Fpr)));
        const u64 Fpn_i = fma2(casa, Zcb,  fma2(saa,  cme_i, mul2(caa, Fpi)));
        const u64 Fmn_r = fma2(casa, mZsb, fma2(saa,  pe_r,  mul2(caa, Fmr)));
        const u64 Fmn_i = fma2(casa, mZcb, fma2(nsaa, pe_i,  mul2(caa, Fmi)));

        // Z' = ca*sa*[Im(Fp e^{-ib}) - Im(Fm e^{ib})] + cos(alpha)*Z
        const u64 Di = fma2(Fmr, nsb2, fma2(Fpr, nsb2, fma2(Fmi, ncb2, mul2(Fpi, cb2))));
        const u64 Zn = fma2(casa, Di, mul2(c_al, Z));

        // --- gradient shift ---
        u64 nFpr = shup64(Fpn_r), nFpi = shup64(Fpn_i);
        if (l0)    { nFpr = 0; nFpi = 0; }
        u64 nFmr = shdn64(Fmn_r), nFmi = shdn64(Fmn_i);
        if (llast) { nFmr = 0; nFmi = 0; }
        Fpr = nFpr; Fpi = nFpi; Fmr = nFmr; Fmi = nFmi; Z = Zn;

        // --- emit [Fp.re, Fp.im, Fm.re, Fm.im, Z] for both rows ---
        if (active) {
            float a0, a1;
            upk(Fpr, a0, a1); o0[0]      = a0; o1[0]      = a1;
            upk(Fpi, a0, a1); o0[CS]     = a0; o1[CS]     = a1;
            upk(Fmr, a0, a1); o0[2 * CS] = a0; o1[2 * CS] = a1;
            upk(Fmi, a0, a1); o0[3 * CS] = a0; o1[3 * CS] = a1;
            upk(Z,   a0, a1); o0[4 * CS] = a0; o1[4 * CS] = a1;
        }
        o0 += 5 * CS; o1 += 5 * CS;
    }
}

extern "C" void kernel_launch(void* const* d_in, const int* in_sizes, int n_in,
                              void* d_out, int out_size)
{
    const float* flip   = (const float*)d_in[0];
    const float* phases = (const float*)d_in[1];
    const float* T1     = (const float*)d_in[2];
    const float* T2     = (const float*)d_in[3];
    const float* B0     = (const float*)d_in[4];
    const float* B1     = (const float*)d_in[5];
    const void*  trp    = d_in[6];
    float* out = (float*)d_out;

    const int threads = 128;                         // 4 warps = 8 batch rows
    const int rows_per_block = (threads / 32) * 2;   // 8
    const int blocks = BATCH / rows_per_block;       // 2048
    epg_kernel<<<blocks, threads>>>(flip, phases, T1, T2, B0, B1, trp, out);
}

// round 4
// speedup vs baseline: 1.3734x; 1.1192x over previous
#include <cuda_runtime.h>

#define N_PULSES 64
#define BATCH    16384
#define N_STATES 21

typedef unsigned long long u64;

// ---- packed f32x2 helpers (Blackwell sm_100+) ----
__device__ __forceinline__ u64 pk(float lo, float hi) {
    u64 r; asm("mov.b64 %0,{%1,%2};" : "=l"(r) : "f"(lo), "f"(hi)); return r;
}
__device__ __forceinline__ void upk(u64 v, float& a, float& b) {
    asm("mov.b64 {%0,%1},%2;" : "=f"(a), "=f"(b) : "l"(v));
}
__device__ __forceinline__ u64 fma2(u64 a, u64 b, u64 c) {
    u64 d; asm("fma.rn.f32x2 %0,%1,%2,%3;" : "=l"(d) : "l"(a), "l"(b), "l"(c)); return d;
}
__device__ __forceinline__ u64 mul2(u64 a, u64 b) {
    u64 d; asm("mul.rn.f32x2 %0,%1,%2;" : "=l"(d) : "l"(a), "l"(b)); return d;
}
#define NEG2(x) ((x) ^ 0x8000000080000000ULL)

__device__ __forceinline__ u64 shup64(u64 v) {
    float a, b; upk(v, a, b);
    a = __shfl_up_sync(0xffffffffu, a, 1);
    b = __shfl_up_sync(0xffffffffu, b, 1);
    return pk(a, b);
}
__device__ __forceinline__ u64 shdn64(u64 v) {
    float a, b; upk(v, a, b);
    a = __shfl_down_sync(0xffffffffu, a, 1);
    b = __shfl_down_sync(0xffffffffu, b, 1);
    return pk(a, b);
}

// One warp serves FOUR batch rows (two f32x2 packs); lane = EPG state.
__global__ __launch_bounds__(128, 5) void epg_kernel(
    const float* __restrict__ flip,
    const float* __restrict__ phases,
    const float* __restrict__ T1,
    const float* __restrict__ T2,
    const float* __restrict__ B0,
    const float* __restrict__ B1,
    const void*  __restrict__ trp,
    float*       __restrict__ out)
{
    // Per-pulse broadcast constants, pre-packed as f32x2 pairs:
    // k[0] = {cb2, sb2}, k[1] = {nsb2, ncb2}, k[2] = {c2b2, s2b2}, k[3] = {ns2b2, nc2b2}
    __shared__ ulonglong2 s_k[N_PULSES][4];
    __shared__ float s_a[N_PULSES];

    const int tid = threadIdx.x;
    if (tid < N_PULSES) {
        float b = phases[tid];
        float sb, cb;
        sincosf(b, &sb, &cb);                 // precise: b in [0, 2pi]
        float c2b = cb * cb - sb * sb;
        float s2b = 2.0f * cb * sb;
        s_k[tid][0] = make_ulonglong2(pk(cb, cb),     pk(sb, sb));
        s_k[tid][1] = make_ulonglong2(pk(-sb, -sb),   pk(-cb, -cb));
        s_k[tid][2] = make_ulonglong2(pk(c2b, c2b),   pk(s2b, s2b));
        s_k[tid][3] = make_ulonglong2(pk(-s2b, -s2b), pk(-c2b, -c2b));
        s_a[tid] = flip[tid];
    }
    __syncthreads();

    const int gw   = (blockIdx.x * blockDim.x + tid) >> 5;   // warp id
    const int lane = tid & 31;
    const int w0 = gw * 4;                                   // four batch rows

    // TR may arrive as int32 or float32 scalar; sniff the bit pattern.
    float TR;
    {
        int   iv = *(const int*)trp;
        float fv = __int_as_float(iv);
        TR = (fv >= 1.0f && fv < 1.0e6f) ? fv : (float)iv;
    }

    const float PC = 2.0f * 3.14159265358979323846f * (1.0f / 1000.0f) * TR;

    // Per-pack loop-invariant constants (pack q covers rows w0+2q, w0+2q+1)
    u64 E1p[2], cpE2[2], spE2[2], addz[2];
    float b1a[2], b1b[2];
    #pragma unroll
    for (int q = 0; q < 2; ++q) {
        const int ra = w0 + 2 * q, rb = ra + 1;
        const float E1x = __expf(-TR / T1[ra]);
        const float E1y = __expf(-TR / T1[rb]);
        const float E2x = __expf(-TR / T2[ra]);
        const float E2y = __expf(-TR / T2[rb]);
        float spx, cpx, spy, cpy;
        sincosf(PC * B0[ra], &spx, &cpx);     // precise: large argument
        sincosf(PC * B0[rb], &spy, &cpy);
        E1p[q]  = pk(E1x, E1y);
        cpE2[q] = pk(cpx * E2x, cpy * E2y);   // E2 fused into precession
        spE2[q] = pk(spx * E2x, spy * E2y);
        addz[q] = (lane == 0) ? pk(1.0f - E1x, 1.0f - E1y) : 0ull;
        b1a[q] = B1[ra]; b1b[q] = B1[rb];
    }

    const u64 HALF  = pk(0.5f, 0.5f);
    const u64 NHALF = pk(-0.5f, -0.5f);

    u64 Fpr[2] = {0, 0}, Fpi[2] = {0, 0}, Fmr[2] = {0, 0}, Fmi[2] = {0, 0};
    u64 Z[2];
    Z[0] = Z[1] = (lane == 0) ? pk(1.0f, 1.0f) : 0ull;

    const size_t CS = (size_t)BATCH * N_STATES;   // component stride (floats)
    float* o = out + (size_t)w0 * N_STATES + lane;
    const bool active = (lane < N_STATES);
    const bool l0     = (lane == 0);
    const bool llast  = (lane == N_STATES - 1);

    for (int p = 0; p < N_PULSES; ++p) {
        const ulonglong2 k0 = s_k[p][0], k1 = s_k[p][1], k2 = s_k[p][2], k3 = s_k[p][3];
        const u64 cb2 = k0.x, sb2 = k0.y, nsb2 = k1.x, ncb2 = k1.y;
        const u64 c2b2 = k2.x, s2b2 = k2.y, ns2b2 = k3.x, nc2b2 = k3.y;
        const float a = s_a[p];

        #pragma unroll
        for (int q = 0; q < 2; ++q) {
            const u64 nspE2 = NEG2(spE2[q]);

            // --- relaxation (E2) fused with off-resonance precession ---
            u64 fr = fma2(Fpi[q], nspE2,   mul2(Fpr[q], cpE2[q]));
            u64 fi = fma2(Fpi[q], cpE2[q], mul2(Fpr[q], spE2[q]));
            u64 mr = fma2(Fmi[q], spE2[q], mul2(Fmr[q], cpE2[q]));
            u64 mi = fma2(Fmi[q], cpE2[q], mul2(Fmr[q], nspE2));
            u64 Zq = fma2(Z[q], E1p[q], addz[q]);

            // --- RF pulse via half-angle identities ---
            float sa0, ca0, sa1, ca1;
            __sincosf(a * b1a[q], &sa0, &ca0);    // alpha (full angle)
            __sincosf(a * b1b[q], &sa1, &ca1);
            const u64 c_al = pk(ca0, ca1);        // cos(alpha)
            const u64 s_al = pk(sa0, sa1);
            const u64 caa  = fma2(c_al, HALF,  HALF);  // cos^2(a/2)
            const u64 saa  = fma2(c_al, NHALF, HALF);  // sin^2(a/2)
            const u64 casa = mul2(s_al, HALF);         // cos(a/2)sin(a/2)
            const u64 nsaa = NEG2(saa);

            // conj(Fm) * e^{2ib}
            const u64 cme_r = fma2(mi, s2b2,  mul2(mr, c2b2));
            const u64 cme_i = fma2(mi, nc2b2, mul2(mr, s2b2));
            // Fp * e^{2ib}
            const u64 pe_r  = fma2(fi, ns2b2, mul2(fr, c2b2));
            const u64 pe_i  = fma2(fi, c2b2,  mul2(fr, s2b2));
            // i Z e^{ib} = (-Z sb, Z cb);  -i Z e^{-ib} = (-Z sb, -Z cb)
            const u64 mZsb = mul2(Zq, nsb2);
            const u64 Zcb  = mul2(Zq, cb2);
            const u64 mZcb = NEG2(Zcb);

            const u64 Fpn_r = fma2(casa, mZsb, fma2(saa,  cme_r, mul2(caa, fr)));
            const u64 Fpn_i = fma2(casa, Zcb,  fma2(saa,  cme_i, mul2(caa, fi)));
            const u64 Fmn_r = fma2(casa, mZsb, fma2(saa,  pe_r,  mul2(caa, mr)));
            const u64 Fmn_i = fma2(casa, mZcb, fma2(nsaa, pe_i,  mul2(caa, mi)));

            // Z' = ca*sa*[Im(Fp e^{-ib}) - Im(Fm e^{ib})] + cos(alpha)*Z
            const u64 Di = fma2(mr, nsb2, fma2(fr, nsb2, fma2(mi, ncb2, mul2(fi, cb2))));
            const u64 Zn = fma2(casa, Di, mul2(c_al, Zq));

            // --- gradient shift ---
            u64 nFpr = shup64(Fpn_r), nFpi = shup64(Fpn_i);
            if (l0)    { nFpr = 0; nFpi = 0; }
            u64 nFmr = shdn64(Fmn_r), nFmi = shdn64(Fmn_i);
            if (llast) { nFmr = 0; nFmi = 0; }
            Fpr[q] = nFpr; Fpi[q] = nFpi; Fmr[q] = nFmr; Fmi[q] = nFmi; Z[q] = Zn;
        }

        // --- emit [Fp.re, Fp.im, Fm.re, Fm.im, Z] for all 4 rows ---
        // All offsets compile-time constants -> immediate-offset STG off one pointer.
        if (active) {
            float x, y;
            #pragma unroll
            for (int q = 0; q < 2; ++q) {
                const size_t rq = (size_t)(2 * q) * N_STATES;
                upk(Fpr[q], x, y); o[rq]          = x; o[rq + N_STATES]          = y;
                upk(Fpi[q], x, y); o[rq + CS]     = x; o[rq + N_STATES + CS]     = y;
                upk(Fmr[q], x, y); o[rq + 2 * CS] = x; o[rq + N_STATES + 2 * CS] = y;
                upk(Fmi[q], x, y); o[rq + 3 * CS] = x; o[rq + N_STATES + 3 * CS] = y;
                upk(Z[q],   x, y); o[rq + 4 * CS] = x; o[rq + N_STATES + 4 * CS] = y;
            }
        }
        o += 5 * CS;
    }
}

extern "C" void kernel_launch(void* const* d_in, const int* in_sizes, int n_in,
                              void* d_out, int out_size)
{
    const float* flip   = (const float*)d_in[0];
    const float* phases = (const float*)d_in[1];
    const float* T1     = (const float*)d_in[2];
    const float* T2     = (const float*)d_in[3];
    const float* B0     = (const float*)d_in[4];
    const float* B1     = (const float*)d_in[5];
    const void*  trp    = d_in[6];
    float* out = (float*)d_out;

    const int threads = 128;                          // 4 warps = 16 batch rows
    const int rows_per_block = (threads / 32) * 4;    // 16
    const int blocks = BATCH / rows_per_block;        // 1024
    epg_kernel<<<blocks, threads>>>(flip, phases, T1, T2, B0, B1, trp, out);
}

// round 7
// speedup vs baseline: 1.4838x; 1.0804x over previous
#include <cuda_runtime.h>

#define N_PULSES 64
#define BATCH    16384
#define N_STATES 21

typedef unsigned long long u64;

// ---- packed f32x2 helpers (Blackwell sm_100+) ----
__device__ __forceinline__ u64 pk(float lo, float hi) {
    u64 r; asm("mov.b64 %0,{%1,%2};" : "=l"(r) : "f"(lo), "f"(hi)); return r;
}
__device__ __forceinline__ void upk(u64 v, float& a, float& b) {
    asm("mov.b64 {%0,%1},%2;" : "=f"(a), "=f"(b) : "l"(v));
}
__device__ __forceinline__ u64 fma2(u64 a, u64 b, u64 c) {
    u64 d; asm("fma.rn.f32x2 %0,%1,%2,%3;" : "=l"(d) : "l"(a), "l"(b), "l"(c)); return d;
}
__device__ __forceinline__ u64 mul2(u64 a, u64 b) {
    u64 d; asm("mul.rn.f32x2 %0,%1,%2;" : "=l"(d) : "l"(a), "l"(b)); return d;
}
#define NEG2(x) ((x) ^ 0x8000000080000000ULL)

// Shift the 4-element-per-lane span UP by one element (new[e] = old[e-1]),
// then zero masked words (row-boundary state 0 positions).
__device__ __forceinline__ void shift_up4(u64& v0, u64& v1, u64 m0, u64 m1) {
    float a0, a1, a2, a3;
    upk(v0, a0, a1); upk(v1, a2, a3);
    float p3 = __shfl_up_sync(0xffffffffu, a3, 1);
    v0 = pk(p3, a0) & m0;
    v1 = pk(a1, a2) & m1;
}
// Shift DOWN by one element (new[e] = old[e+1]), zero at state-20 positions.
__device__ __forceinline__ void shift_dn4(u64& v0, u64& v1, u64 m0, u64 m1) {
    float a0, a1, a2, a3;
    upk(v0, a0, a1); upk(v1, a2, a3);
    float n0 = __shfl_down_sync(0xffffffffu, a0, 1);
    v0 = pk(a1, a2) & m0;
    v1 = pk(a3, n0) & m1;
}

// One warp serves FOUR batch rows = 84 contiguous floats per component.
// Lane l owns elements 4l..4l+3 of that span (21 active lanes), held as two
// f32x2 packs per variable. Stores are single STG.128 per component.
__global__ __launch_bounds__(128, 5) void epg_kernel(
    const float* __restrict__ flip,
    const float* __restrict__ phases,
    const float* __restrict__ T1,
    const float* __restrict__ T2,
    const float* __restrict__ B0,
    const float* __restrict__ B1,
    const void*  __restrict__ trp,
    float*       __restrict__ out)
{
    // Per-pulse broadcast constants, pre-packed f32x2:
    // k[0]={cb2,sb2}, k[1]={nsb2,ncb2}, k[2]={c2b2,s2b2}, k[3]={ns2b2,nc2b2}
    __shared__ ulonglong2 s_k[N_PULSES][4];
    __shared__ float s_a[N_PULSES];

    const int tid = threadIdx.x;
    if (tid < N_PULSES) {
        float b = phases[tid];
        float sb, cb;
        sincosf(b, &sb, &cb);                 // precise: b in [0, 2pi]
        float c2b = cb * cb - sb * sb;
        float s2b = 2.0f * cb * sb;
        s_k[tid][0] = make_ulonglong2(pk(cb, cb),     pk(sb, sb));
        s_k[tid][1] = make_ulonglong2(pk(-sb, -sb),   pk(-cb, -cb));
        s_k[tid][2] = make_ulonglong2(pk(c2b, c2b),   pk(s2b, s2b));
        s_k[tid][3] = make_ulonglong2(pk(-s2b, -s2b), pk(-c2b, -c2b));
        s_a[tid] = flip[tid];
    }
    __syncthreads();

    const int gw   = (blockIdx.x * blockDim.x + tid) >> 5;   // warp id
    const int lane = tid & 31;
    const int w0   = gw * 4;                                 // four batch rows

    // TR may arrive as int32 or float32 scalar; sniff the bit pattern.
    float TR;
    {
        int   iv = *(const int*)trp;
        float fv = __int_as_float(iv);
        TR = (fv >= 1.0f && fv < 1.0e6f) ? fv : (float)iv;
    }
    const float PC = 2.0f * 3.14159265358979323846f * (1.0f / 1000.0f) * TR;

    // ---- per-element init (4 elements per lane) ----
    float E1e[4], cpe[4], spe[4], adze[4], z0e[4], b1e[4];
    u64 mup[2], mdn[2];
    mup[0] = mup[1] = mdn[0] = mdn[1] = ~0ull;
    #pragma unroll
    for (int j = 0; j < 4; ++j) {
        const int e  = 4 * lane + j;
        int dr = e / 21; if (dr > 3) dr = 3;      // clamp for inactive lanes
        const int r  = w0 + dr;
        const int s  = e - 21 * (e / 21);
        const float E1 = __expf(-TR / T1[r]);
        const float E2 = __expf(-TR / T2[r]);
        float sp, cp;
        sincosf(PC * B0[r], &sp, &cp);            // precise: large argument
        E1e[j] = E1;
        cpe[j] = cp * E2;                         // E2 fused into precession
        spe[j] = sp * E2;
        b1e[j] = B1[r];
        adze[j] = (s == 0) ? (1.0f - E1) : 0.0f;
        z0e[j]  = (s == 0) ? 1.0f : 0.0f;
        const u64 wordmask = (j & 1) ? 0x00000000FFFFFFFFull : 0xFFFFFFFF00000000ull;
        if (s == 0)  mup[j >> 1] &= wordmask;     // zero Fp at state 0
        if (s == 20) mdn[j >> 1] &= wordmask;     // zero Fm at last state
    }
    u64 E1p[2], cpE2[2], spE2[2], addz[2];
    u64 Z[2];
    #pragma unroll
    for (int j2 = 0; j2 < 2; ++j2) {
        E1p[j2]  = pk(E1e[2 * j2], E1e[2 * j2 + 1]);
        cpE2[j2] = pk(cpe[2 * j2], cpe[2 * j2 + 1]);
        spE2[j2] = pk(spe[2 * j2], spe[2 * j2 + 1]);
        addz[j2] = pk(adze[2 * j2], adze[2 * j2 + 1]);
        Z[j2]    = pk(z0e[2 * j2], z0e[2 * j2 + 1]);
    }

    const u64 HALF  = pk(0.5f, 0.5f);
    const u64 NHALF = pk(-0.5f, -0.5f);

    u64 Fpr[2] = {0, 0}, Fpi[2] = {0, 0}, Fmr[2] = {0, 0}, Fmi[2] = {0, 0};

    const size_t CS = (size_t)BATCH * N_STATES;   // component stride (floats)
    float* o = out + (size_t)w0 * N_STATES + 4 * lane;   // 16B-aligned
    const bool active = (lane < N_STATES);

    for (int p = 0; p < N_PULSES; ++p) {
        const ulonglong2 k0 = s_k[p][0], k1 = s_k[p][1], k2 = s_k[p][2], k3 = s_k[p][3];
        const u64 cb2 = k0.x, sb2 = k0.y, nsb2 = k1.x, ncb2 = k1.y;
        const u64 c2b2 = k2.x, s2b2 = k2.y, ns2b2 = k3.x, nc2b2 = k3.y;
        const float a = s_a[p];

        // RF rotation angles per element (row-dependent via B1)
        float sae[4], cae[4];
        #pragma unroll
        for (int j = 0; j < 4; ++j) __sincosf(a * b1e[j], &sae[j], &cae[j]);

        #pragma unroll
        for (int j2 = 0; j2 < 2; ++j2) {
            const u64 nspE2 = NEG2(spE2[j2]);

            // --- relaxation (E2) fused with off-resonance precession ---
            u64 fr = fma2(Fpi[j2], nspE2,     mul2(Fpr[j2], cpE2[j2]));
            u64 fi = fma2(Fpi[j2], cpE2[j2],  mul2(Fpr[j2], spE2[j2]));
            u64 mr = fma2(Fmi[j2], spE2[j2],  mul2(Fmr[j2], cpE2[j2]));
            u64 mi = fma2(Fmi[j2], cpE2[j2],  mul2(Fmr[j2], nspE2));
            u64 Zq = fma2(Z[j2], E1p[j2], addz[j2]);

            // --- RF pulse via half-angle identities ---
            const u64 c_al = pk(cae[2 * j2], cae[2 * j2 + 1]);  // cos(alpha)
            const u64 s_al = pk(sae[2 * j2], sae[2 * j2 + 1]);  // sin(alpha)
            const u64 caa  = fma2(c_al, HALF,  HALF);   // cos^2(a/2)
            const u64 saa  = fma2(c_al, NHALF, HALF);   // sin^2(a/2)
            const u64 casa = mul2(s_al, HALF);          // cos(a/2)sin(a/2)
            const u64 nsaa = NEG2(saa);

            // conj(Fm) * e^{2ib}
            const u64 cme_r = fma2(mi, s2b2,  mul2(mr, c2b2));
            const u64 cme_i = fma2(mi, nc2b2, mul2(mr, s2b2));
            // Fp * e^{2ib}
            const u64 pe_r  = fma2(fi, ns2b2, mul2(fr, c2b2));
            const u64 pe_i  = fma2(fi, c2b2,  mul2(fr, s2b2));
            // i Z e^{ib} = (-Z sb, Z cb);  -i Z e^{-ib} = (-Z sb, -Z cb)
            const u64 mZsb = mul2(Zq, nsb2);
            const u64 Zcb  = mul2(Zq, cb2);
            const u64 mZcb = NEG2(Zcb);

            Fpr[j2] = fma2(casa, mZsb, fma2(saa,  cme_r, mul2(caa, fr)));
            Fpi[j2] = fma2(casa, Zcb,  fma2(saa,  cme_i, mul2(caa, fi)));
            Fmr[j2] = fma2(casa, mZsb, fma2(saa,  pe_r,  mul2(caa, mr)));
            Fmi[j2] = fma2(casa, mZcb, fma2(nsaa, pe_i,  mul2(caa, mi)));

            // Z' = ca*sa*[Im(Fp e^{-ib}) - Im(Fm e^{ib})] + cos(alpha)*Z
            const u64 Di = fma2(mr, nsb2, fma2(fr, nsb2, fma2(mi, ncb2, mul2(fi, cb2))));
            Z[j2] = fma2(casa, Di, mul2(c_al, Zq));
        }

        // --- gradient shift across the whole 84-element span ---
        shift_up4(Fpr[0], Fpr[1], mup[0], mup[1]);
        shift_up4(Fpi[0], Fpi[1], mup[0], mup[1]);
        shift_dn4(Fmr[0], Fmr[1], mdn[0], mdn[1]);
        shift_dn4(Fmi[0], Fmi[1], mdn[0], mdn[1]);

        // --- emit [Fp.re, Fp.im, Fm.re, Fm.im, Z]: one STG.128 per component ---
        if (active) {
            float x0, x1, x2, x3;
            upk(Fpr[0], x0, x1); upk(Fpr[1], x2, x3);
            *(float4*)(o)          = make_float4(x0, x1, x2, x3);
            upk(Fpi[0], x0, x1); upk(Fpi[1], x2, x3);
            *(float4*)(o + CS)     = make_float4(x0, x1, x2, x3);
            upk(Fmr[0], x0, x1); upk(Fmr[1], x2, x3);
            *(float4*)(o + 2 * CS) = make_float4(x0, x1, x2, x3);
            upk(Fmi[0], x0, x1); upk(Fmi[1], x2, x3);
            *(float4*)(o + 3 * CS) = make_float4(x0, x1, x2, x3);
            upk(Z[0], x0, x1);   upk(Z[1], x2, x3);
            *(float4*)(o + 4 * CS) = make_float4(x0, x1, x2, x3);
        }
        o += 5 * CS;
    }
}

extern "C" void kernel_launch(void* const* d_in, const int* in_sizes, int n_in,
                              void* d_out, int out_size)
{
    const float* flip   = (const float*)d_in[0];
    const float* phases = (const float*)d_in[1];
    const float* T1     = (const float*)d_in[2];
    const float* T2     = (const float*)d_in[3];
    const float* B0     = (const float*)d_in[4];
    const float* B1     = (const float*)d_in[5];
    const void*  trp    = d_in[6];
    float* out = (float*)d_out;

    const int threads = 128;                          // 4 warps = 16 batch rows
    const int rows_per_block = (threads / 32) * 4;    // 16
    const int blocks = BATCH / rows_per_block;        // 1024
    epg_kernel<<<blocks, threads>>>(flip, phases, T1, T2, B0, B1, trp, out);
}